// round 9
// baseline (speedup 1.0000x reference)
#include <cuda_runtime.h>

#define RAYS 16384
#define SAMP 64
#define NP (RAYS*SAMP)
#define GS 128
#define EE 16
#define HH 64
#define CIN 18
#define BP 128            // points per block
#define NT 256            // threads per block (2 threads per point in scalar phases)

// Scratch (device globals; no allocation allowed)
__device__ float g_rgb[NP*3];
__device__ float g_sigma[NP];

// ---- dynamic smem float offsets ----
#define OFF_W1T   0        // [16][64]
#define OFF_W1    1024     // [64][16]
#define OFF_W3T   2048     // [64][16]
#define OFF_B1    3072
#define OFF_B2    3136
#define OFF_B3    3200
#define OFF_CB1   3216
#define OFF_CB2   3280
#define OFF_CB3   3344
#define OFF_CW3T  3348     // [64][4]
#define OFF_WBIG  3604     // [64][64]  Wt2 -> W2 -> CW1t -> CWt2
#define OFF_F     7700     // [18][128]
#define OFF_HA    10004    // [64][128]
#define OFF_HB    18196    // [64][128] (also 64x65 stage area)
#define SM_FLOATS 26388
#define SM_BYTES  (SM_FLOATS*4)

extern __shared__ float sm[];

typedef unsigned long long u64;
#define FULLMASK 0xffffffffu

__device__ __forceinline__ u64 pack2(float x, float y) {
    u64 d;
    asm("mov.b64 %0, {%1, %2};" : "=l"(d) : "f"(x), "f"(y));
    return d;
}
__device__ __forceinline__ u64 fma2(u64 a, u64 b, u64 c) {
    u64 d;
    asm("fma.rn.f32x2 %0, %1, %2, %3;" : "=l"(d) : "l"(a), "l"(b), "l"(c));
    return d;
}
__device__ __forceinline__ float2 unpack2(u64 v) {
    float2 r;
    asm("mov.b64 {%0, %1}, %2;" : "=f"(r.x), "=f"(r.y) : "l"(v));
    return r;
}

__device__ __forceinline__ float softplus100(float z) {
    float a = 100.0f * z;
    float sp = fmaxf(a, 0.0f) + __logf(1.0f + __expf(-fabsf(a)));
    return 0.01f * sp;
}

// Tile: 4 points x 8 units per thread (8 warps cover 64 units).
// Warp shares one unit group -> weight LDS are warp-broadcast, consumed as
// packed u64 pairs. MODE 0: softplus100(acc+b); 1: relu(acc+b);
// 2: dz1 = acc * (1 - exp(-100*h_prev)), h_prev read from Hout.
template<int K, int MODE>
__device__ __forceinline__ void gemm128(const float* __restrict__ Wt,
                                        const float* __restrict__ Hin,
                                        float* __restrict__ Hout,
                                        const float* __restrict__ bias,
                                        int tt)
{
    const int pt0 = (tt & 31) * 4;
    const int u0  = (tt >> 5) * 8;
    u64 acc[4][4];
    #pragma unroll
    for (int i = 0; i < 4; i++)
        #pragma unroll
        for (int j = 0; j < 4; j++) acc[i][j] = 0ull;

    #pragma unroll 8
    for (int k = 0; k < K; k++) {
        float4 av = *(const float4*)&Hin[k*BP + pt0];
        u64 a[4] = {pack2(av.x, av.x), pack2(av.y, av.y),
                    pack2(av.z, av.z), pack2(av.w, av.w)};
        const ulonglong2* wp = (const ulonglong2*)&Wt[k*64 + u0];
        ulonglong2 W01 = wp[0], W23 = wp[1];
        u64 w[4] = {W01.x, W01.y, W23.x, W23.y};
        #pragma unroll
        for (int i = 0; i < 4; i++)
            #pragma unroll
            for (int j = 0; j < 4; j++)
                acc[i][j] = fma2(a[i], w[j], acc[i][j]);
    }

    float4 bi[2];
    if (MODE != 2) {
        bi[0] = *(const float4*)&bias[u0];
        bi[1] = *(const float4*)&bias[u0 + 4];
    }
    const float* bs = (const float*)bi;

    #pragma unroll
    for (int j = 0; j < 4; j++) {
        float2 r0 = unpack2(acc[0][j]);
        float2 r1 = unpack2(acc[1][j]);
        float2 r2 = unpack2(acc[2][j]);
        float2 r3 = unpack2(acc[3][j]);
        #pragma unroll
        for (int b = 0; b < 2; b++) {
            const int u = u0 + 2*j + b;
            float z0 = b ? r0.y : r0.x;
            float z1 = b ? r1.y : r1.x;
            float z2 = b ? r2.y : r2.x;
            float z3 = b ? r3.y : r3.x;
            float* orow = &Hout[u*BP + pt0];
            float res0, res1, res2, res3;
            if (MODE == 2) {
                float4 vin = *(const float4*)orow;
                res0 = z0 * (1.0f - __expf(-100.0f * vin.x));
                res1 = z1 * (1.0f - __expf(-100.0f * vin.y));
                res2 = z2 * (1.0f - __expf(-100.0f * vin.z));
                res3 = z3 * (1.0f - __expf(-100.0f * vin.w));
            } else {
                float bj = bs[2*j + b];
                if (MODE == 0) {
                    res0 = softplus100(z0 + bj);
                    res1 = softplus100(z1 + bj);
                    res2 = softplus100(z2 + bj);
                    res3 = softplus100(z3 + bj);
                } else {
                    res0 = fmaxf(z0 + bj, 0.0f);
                    res1 = fmaxf(z1 + bj, 0.0f);
                    res2 = fmaxf(z2 + bj, 0.0f);
                    res3 = fmaxf(z3 + bj, 0.0f);
                }
            }
            *(float4*)orow = make_float4(res0, res1, res2, res3);
        }
    }
}

__global__ void __launch_bounds__(NT, 2)
points_kernel(const float* __restrict__ rays_o,
              const float* __restrict__ rays_d,
              const float* __restrict__ grid,
              const float* __restrict__ w1, const float* __restrict__ b1,
              const float* __restrict__ w2, const float* __restrict__ b2,
              const float* __restrict__ w3, const float* __restrict__ b3,
              const float* __restrict__ cw1, const float* __restrict__ cb1,
              const float* __restrict__ cw2, const float* __restrict__ cb2,
              const float* __restrict__ cw3, const float* __restrict__ cb3,
              const float* __restrict__ beta,
              const int* __restrict__ nearp,
              const int* __restrict__ farp,
              float* __restrict__ out)
{
    const int tt = threadIdx.x;
    const int pc = tt >> 1;          // point within tile (2 threads/point)
    const int kh = tt & 1;           // k-half / corner-half id
    const int p  = blockIdx.x * BP + pc;
    const int r  = p >> 6;
    const int s  = p & 63;

    // ---------- phase 0a: weight loads + stage + gather ----------
    for (int t = tt; t < 1024; t += NT) { int i = t >> 6, j = t & 63; sm[OFF_W1T + t] = w1[j*16 + i]; }
    for (int t = tt; t < 1024; t += NT) sm[OFF_W1 + t] = w1[t];
    for (int t = tt; t < 1024; t += NT) { int k = t >> 4, i = t & 15; sm[OFF_W3T + t] = w3[i*64 + k]; }
    for (int t = tt; t < 64; t += NT) {
        sm[OFF_B1 + t] = b1[t]; sm[OFF_B2 + t] = b2[t];
        sm[OFF_CB1 + t] = cb1[t]; sm[OFF_CB2 + t] = cb2[t];
    }
    if (tt < 16) sm[OFF_B3 + tt] = b3[tt];
    if (tt < 4)  sm[OFF_CB3 + tt] = (tt < 3) ? cb3[tt] : 0.0f;
    for (int t = tt; t < 256; t += NT) { int k = t >> 2, i = t & 3; sm[OFF_CW3T + t] = (i < 3) ? cw3[i*64 + k] : 0.0f; }
    // stage w2 coalesced with pitch 65 (for transpose into Wt2)
    for (int t = tt; t < 4096; t += NT) { int j = t >> 6, k = t & 63; sm[OFF_HB + j*65 + k] = w2[t]; }

    // ---- per-point setup (both threads of the pair compute) ----
    float nearf = (float)nearp[0];
    float farf  = (float)farp[0];
    float dt    = (farf - nearf) * (1.0f / (float)SAMP);
    float tmid  = nearf + ((float)s + 0.5f) * dt;

    float f[3]; int i0[3]; bool inb[3];
    #pragma unroll
    for (int c = 0; c < 3; c++) {
        float o = rays_o[3*r + c];
        float d = rays_d[3*r + c];
        float xcc = __fadd_rn(o, __fmul_rn(tmid, d));
        float graw = __fmul_rn(__fmul_rn(__fadd_rn(__fdiv_rn(xcc, 1.3f), 1.0f), 0.5f), 127.0f);
        inb[c] = (graw >= 0.0f) && (graw <= 127.0f);
        float gg = fminf(fmaxf(graw, 0.0f), 127.0f);
        int ii = (int)floorf(gg);
        if (ii > 126) ii = 126;
        i0[c] = ii;
        f[c] = gg - (float)ii;
    }
    const bool mask = inb[0] && inb[1] && inb[2];
    const int base000 = (i0[0]*GS + i0[1])*GS + i0[2];

    float wx[2] = {1.0f - f[0], f[0]};
    float wy[2] = {1.0f - f[1], f[1]};
    const float wzh = kh ? f[2] : (1.0f - f[2]);   // this thread's dz == kh

    // ---- trilinear gather: 4 corners per thread, pair-combined ----
    {
        float emb[EE];
        #pragma unroll
        for (int i = 0; i < EE; i++) emb[i] = 0.0f;
        #pragma unroll
        for (int c = 0; c < 4; c++) {
            const int dx = (c >> 1) & 1, dy = c & 1;
            const float w = wx[dx] * wy[dy] * wzh;
            const float4* cp = reinterpret_cast<const float4*>(
                grid + (size_t)(base000 + dx*(GS*GS) + dy*GS + kh) * EE);
            #pragma unroll
            for (int q = 0; q < 4; q++) {
                float4 v = cp[q];
                emb[4*q+0] = fmaf(w, v.x, emb[4*q+0]);
                emb[4*q+1] = fmaf(w, v.y, emb[4*q+1]);
                emb[4*q+2] = fmaf(w, v.z, emb[4*q+2]);
                emb[4*q+3] = fmaf(w, v.w, emb[4*q+3]);
            }
        }
        #pragma unroll
        for (int i = 0; i < EE; i++) emb[i] += __shfl_xor_sync(FULLMASK, emb[i], 1);
        #pragma unroll
        for (int i = 0; i < 8; i++) sm[OFF_F + (kh*8 + i)*BP + pc] = emb[kh*8 + i];
    }
    __syncthreads();

    // ---------- phase 0b: transpose Wt2 + L1 fwd GEMM ----------
    for (int t = tt; t < 4096; t += NT) { int k = t >> 6, j = t & 63; sm[OFF_WBIG + k*64 + j] = sm[OFF_HB + j*65 + k]; }
    gemm128<16, 0>(sm + OFF_W1T, sm + OFF_F, sm + OFF_HA, sm + OFF_B1, tt);
    __syncthreads();

    // ---------- phase 2: L2 fwd GEMM ----------
    gemm128<64, 0>(sm + OFF_WBIG, sm + OFF_HA, sm + OFF_HB, sm + OFF_B2, tt);
    __syncthreads();

    // ---------- phase 3: load W2 (bwd layout) + L3 fwd (pair-split k) + dz2 + sigma ----------
    for (int t = tt; t < 4096; t += NT) sm[OFF_WBIG + t] = w2[t];
    {
        u64 op[8];
        #pragma unroll
        for (int i = 0; i < 8; i++) op[i] = 0ull;
        #pragma unroll 8
        for (int kk = 0; kk < 32; kk++) {
            const int k = kh*32 + kk;
            float h2k = sm[OFF_HB + k*BP + pc];
            u64 ak = pack2(h2k, h2k);
            const ulonglong2* wr = reinterpret_cast<const ulonglong2*>(&sm[OFF_W3T + k*16]);
            ulonglong2 W0 = wr[0], W1v = wr[1];
            op[0] = fma2(ak, W0.x, op[0]);
            op[1] = fma2(ak, W0.y, op[1]);
            op[2] = fma2(ak, W1v.x, op[2]);
            op[3] = fma2(ak, W1v.y, op[3]);
            ulonglong2 W2v = wr[2], W3v = wr[3];
            op[4] = fma2(ak, W2v.x, op[4]);
            op[5] = fma2(ak, W2v.y, op[5]);
            op[6] = fma2(ak, W3v.x, op[6]);
            op[7] = fma2(ak, W3v.y, op[7]);
            float dz2 = sm[OFF_W3T + k*16 + 0] * (1.0f - __expf(-100.0f * h2k));
            sm[OFF_HB + k*BP + pc] = dz2;
        }
        float o[16];
        #pragma unroll
        for (int i2 = 0; i2 < 8; i2++) {
            float2 v = unpack2(op[i2]);
            o[2*i2+0] = v.x;
            o[2*i2+1] = v.y;
        }
        #pragma unroll
        for (int i = 0; i < 16; i++) o[i] += __shfl_xor_sync(FULLMASK, o[i], 1);
        if (kh == 0) {
            #pragma unroll
            for (int i = 1; i <= 8; i++) sm[OFF_F + (i-1)*BP + pc] = o[i] + sm[OFF_B3 + i];
        } else {
            #pragma unroll
            for (int i = 9; i < 16; i++) sm[OFF_F + (i-1)*BP + pc] = o[i] + sm[OFF_B3 + i];
            float sdf = o[0] + sm[OFF_B3 + 0];
            float be  = 0.015f + fabsf(beta[0]);
            float as  = fabsf(sdf);
            float em1 = __expf(-as / be) - 1.0f;
            float sgn = (sdf > 0.0f) ? 1.0f : ((sdf < 0.0f) ? -1.0f : 0.0f);
            float sg  = (0.5f + 0.5f * sgn * em1) / be;
            g_sigma[p] = mask ? sg : 0.0f;
        }
    }
    __syncthreads();

    // ---------- phase 4: L2 bwd GEMM (dz1 into HA) ----------
    gemm128<64, 2>(sm + OFF_WBIG, sm + OFF_HB, sm + OFF_HA, sm + OFF_B1, tt);
    __syncthreads();

    // ---------- phase 5: load CW1t + stage cw2 + d_emb (pair-split) + trilinear bwd ----------
    for (int t = tt; t < 18*64; t += NT) { int i = t >> 6, j = t & 63; sm[OFF_WBIG + t] = cw1[j*CIN + i]; }
    for (int t = tt; t < 4096; t += NT) { int j = t >> 6, k = t & 63; sm[OFF_HB + j*65 + k] = cw2[t]; }
    {
        u64 op[8];
        #pragma unroll
        for (int i = 0; i < 8; i++) op[i] = 0ull;
        #pragma unroll 8
        for (int jj = 0; jj < 32; jj++) {
            const int j = kh*32 + jj;
            float d = sm[OFF_HA + j*BP + pc];
            u64 ak = pack2(d, d);
            const ulonglong2* wr = reinterpret_cast<const ulonglong2*>(&sm[OFF_W1 + j*16]);
            ulonglong2 W0 = wr[0], W1v = wr[1];
            op[0] = fma2(ak, W0.x, op[0]);
            op[1] = fma2(ak, W0.y, op[1]);
            op[2] = fma2(ak, W1v.x, op[2]);
            op[3] = fma2(ak, W1v.y, op[3]);
            ulonglong2 W2v = wr[2], W3v = wr[3];
            op[4] = fma2(ak, W2v.x, op[4]);
            op[5] = fma2(ak, W2v.y, op[5]);
            op[6] = fma2(ak, W3v.x, op[6]);
            op[7] = fma2(ak, W3v.y, op[7]);
        }
        float o[16];
        #pragma unroll
        for (int i2 = 0; i2 < 8; i2++) {
            float2 v = unpack2(op[i2]);
            o[2*i2+0] = v.x;
            o[2*i2+1] = v.y;
        }
        #pragma unroll
        for (int i = 0; i < 16; i++) o[i] += __shfl_xor_sync(FULLMASK, o[i], 1);

        // trilinear backward: own 4 corners (dz == kh), pair-combined
        float wz2[2] = {1.0f - f[2], f[2]};
        float gx = 0.0f, gy = 0.0f, gz = 0.0f;
        const float sz = kh ? 1.0f : -1.0f;
        #pragma unroll
        for (int c = 0; c < 4; c++) {
            const int dx = (c >> 1) & 1, dy = c & 1;
            const float4* cp = reinterpret_cast<const float4*>(
                grid + (size_t)(base000 + dx*(GS*GS) + dy*GS + kh) * EE);
            float dot = 0.0f;
            #pragma unroll
            for (int q = 0; q < 4; q++) {
                float4 v = cp[q];
                dot = fmaf(o[4*q+0], v.x, dot);
                dot = fmaf(o[4*q+1], v.y, dot);
                dot = fmaf(o[4*q+2], v.z, dot);
                dot = fmaf(o[4*q+3], v.w, dot);
            }
            float sx = dx ? 1.0f : -1.0f;
            float sy = dy ? 1.0f : -1.0f;
            gx = fmaf(sx * wy[dy] * wzh,      dot, gx);
            gy = fmaf(wx[dx] * sy * wz2[kh],  dot, gy);
            gz = fmaf(wx[dx] * wy[dy] * sz,   dot, gz);
        }
        gx += __shfl_xor_sync(FULLMASK, gx, 1);
        gy += __shfl_xor_sync(FULLMASK, gy, 1);
        gz += __shfl_xor_sync(FULLMASK, gz, 1);

        const float K = 48.846153846153847f;   // 0.5*(G-1)/BOUND
        float dX = gx * (inb[0] ? K : 0.0f);
        float dY = gy * (inb[1] ? K : 0.0f);
        float dZ = gz * (inb[2] ? K : 0.0f);
        float nn  = fmaxf(sqrtf(dX*dX + dY*dY + dZ*dZ), 1e-12f);
        float inv = 1.0f / nn;
        if (kh == 0) {
            out[RAYS*8 + 3*p + 0] = dX;
            out[RAYS*8 + 3*p + 1] = dY;
            out[RAYS*8 + 3*p + 2] = dZ;
            sm[OFF_F + 15*BP + pc] = dX * inv;
        } else {
            sm[OFF_F + 16*BP + pc] = dY * inv;
            sm[OFF_F + 17*BP + pc] = dZ * inv;
        }
    }
    __syncthreads();

    // ---------- phase 6: color L1 GEMM ----------
    gemm128<18, 1>(sm + OFF_WBIG, sm + OFF_F, sm + OFF_HA, sm + OFF_CB1, tt);
    __syncthreads();

    // ---------- phase 7: transpose CWt2 ----------
    for (int t = tt; t < 4096; t += NT) { int k = t >> 6, j = t & 63; sm[OFF_WBIG + k*64 + j] = sm[OFF_HB + j*65 + k]; }
    __syncthreads();

    // ---------- phase 8: color L2 GEMM ----------
    gemm128<64, 1>(sm + OFF_WBIG, sm + OFF_HA, sm + OFF_HB, sm + OFF_CB2, tt);
    __syncthreads();

    // ---------- phase 9: color L3 (pair-split k) ----------
    {
        float a0 = 0.0f, a1 = 0.0f, a2 = 0.0f;
        #pragma unroll 8
        for (int kk = 0; kk < 32; kk++) {
            const int k = kh*32 + kk;
            float hk = sm[OFF_HB + k*BP + pc];
            float4 cw = *(const float4*)&sm[OFF_CW3T + k*4];
            a0 = fmaf(hk, cw.x, a0);
            a1 = fmaf(hk, cw.y, a1);
            a2 = fmaf(hk, cw.z, a2);
        }
        a0 += __shfl_xor_sync(FULLMASK, a0, 1);
        a1 += __shfl_xor_sync(FULLMASK, a1, 1);
        a2 += __shfl_xor_sync(FULLMASK, a2, 1);
        if (kh == 0) {
            a0 += sm[OFF_CB3 + 0];
            a1 += sm[OFF_CB3 + 1];
            a2 += sm[OFF_CB3 + 2];
            g_rgb[3*p + 0] = 1.0f / (1.0f + __expf(-a0));
            g_rgb[3*p + 1] = 1.0f / (1.0f + __expf(-a1));
            g_rgb[3*p + 2] = 1.0f / (1.0f + __expf(-a2));
        }
    }
}

// ---------------- render: 1 block (64 threads) per ray, shfl scan ----------------
__global__ void __launch_bounds__(64)
render_kernel(const float* __restrict__ rays_d_norm,
              const int* __restrict__ nearp, const int* __restrict__ farp,
              float* __restrict__ out)
{
    __shared__ float red[64*8];
    __shared__ float warp0_total;
    const int r = blockIdx.x;
    const int s = threadIdx.x;
    const int lane = s & 31;
    const int wrp  = s >> 5;
    const int p = r * SAMP + s;

    float nearf = (float)nearp[0];
    float farf  = (float)farp[0];
    float dt    = (farf - nearf) * (1.0f / (float)SAMP);
    const float* grads = out + RAYS*8;

    float dd = g_sigma[p] * dt;

    float cs = dd;
    #pragma unroll
    for (int o = 1; o < 32; o <<= 1) {
        float v = __shfl_up_sync(0xffffffffu, cs, o);
        if (lane >= o) cs += v;
    }
    if (wrp == 0 && lane == 31) warp0_total = cs;
    __syncthreads();
    if (wrp == 1) cs += warp0_total;

    float T = __expf(-(cs - dd));
    float w = (1.0f - __expf(-dd)) * T;

    float rgb0 = g_rgb[3*p + 0], rgb1 = g_rgb[3*p + 1], rgb2 = g_rgb[3*p + 2];
    float gx = grads[3*p + 0], gy = grads[3*p + 1], gz = grads[3*p + 2];
    float nn = fmaxf(sqrtf(gx*gx + gy*gy + gz*gz), 1e-12f);
    float wi = w / nn;
    float tm = nearf + ((float)s + 0.5f) * dt;

    red[s*8 + 0] = w * rgb0;
    red[s*8 + 1] = w * rgb1;
    red[s*8 + 2] = w * rgb2;
    red[s*8 + 3] = w * tm;
    red[s*8 + 4] = wi * gx;
    red[s*8 + 5] = wi * gy;
    red[s*8 + 6] = wi * gz;
    red[s*8 + 7] = w;
    __syncthreads();

    #pragma unroll
    for (int stride = 32; stride >= 1; stride >>= 1) {
        if (s < stride) {
            float4 a0 = *(float4*)&red[s*8];
            float4 a1 = *(float4*)&red[s*8 + 4];
            float4 b0 = *(float4*)&red[(s+stride)*8];
            float4 b1 = *(float4*)&red[(s+stride)*8 + 4];
            a0.x += b0.x; a0.y += b0.y; a0.z += b0.z; a0.w += b0.w;
            a1.x += b1.x; a1.y += b1.y; a1.z += b1.z; a1.w += b1.w;
            *(float4*)&red[s*8] = a0;
            *(float4*)&red[s*8 + 4] = a1;
        }
        __syncthreads();
    }

    if (s == 0) {
        float ir = 1.0f / rays_d_norm[r];
        out[8*r + 0] = red[0];
        out[8*r + 1] = red[1];
        out[8*r + 2] = red[2];
        out[8*r + 3] = red[3] * ir;
        out[8*r + 4] = red[4];
        out[8*r + 5] = red[5];
        out[8*r + 6] = red[6];
        out[8*r + 7] = red[7];
    }
}

extern "C" void kernel_launch(void* const* d_in, const int* in_sizes, int n_in,
                              void* d_out, int out_size)
{
    const float* rays_o      = (const float*)d_in[0];
    const float* rays_d      = (const float*)d_in[1];
    const float* rays_d_norm = (const float*)d_in[2];
    const float* grid        = (const float*)d_in[3];
    const float* sw1 = (const float*)d_in[4];
    const float* sb1 = (const float*)d_in[5];
    const float* sw2 = (const float*)d_in[6];
    const float* sb2 = (const float*)d_in[7];
    const float* sw3 = (const float*)d_in[8];
    const float* sb3 = (const float*)d_in[9];
    const float* cw1 = (const float*)d_in[10];
    const float* cb1 = (const float*)d_in[11];
    const float* cw2 = (const float*)d_in[12];
    const float* cb2 = (const float*)d_in[13];
    const float* cw3 = (const float*)d_in[14];
    const float* cb3 = (const float*)d_in[15];
    const float* beta  = (const float*)d_in[16];
    const int*   nearp = (const int*)d_in[17];
    const int*   farp  = (const int*)d_in[18];
    float* out = (float*)d_out;

    cudaFuncSetAttribute(points_kernel,
                         cudaFuncAttributeMaxDynamicSharedMemorySize, SM_BYTES);

    points_kernel<<<NP/BP, NT, SM_BYTES>>>(rays_o, rays_d, grid,
                                           sw1, sb1, sw2, sb2, sw3, sb3,
                                           cw1, cb1, cw2, cb2, cw3, cb3,
                                           beta, nearp, farp, out);
    render_kernel<<<RAYS, 64>>>(rays_d_norm, nearp, farp, out);
}

// round 11
// speedup vs baseline: 1.0705x; 1.0705x over previous
#include <cuda_runtime.h>

#define RAYS 16384
#define SAMP 64
#define NP (RAYS*SAMP)
#define GS 128
#define EE 16
#define HH 64
#define CIN 18
#define BP 128            // points per block = 2 rays
#define NT 128            // threads per block

// ---- dynamic smem float offsets ----
#define OFF_W1T   0        // [16][64]
#define OFF_W1    1024     // [64][16]
#define OFF_W3T   2048     // [64][16]
#define OFF_B1    3072
#define OFF_B2    3136
#define OFF_B3    3200
#define OFF_CB1   3216
#define OFF_CB2   3280
#define OFF_CB3   3344
#define OFF_CW3T  3348     // [64][4]
#define OFF_WBIG  3604     // [64][64]  Wt2 -> W2 -> CW1t -> CWt2
#define OFF_F     7700     // [18][128]
#define OFF_HA    10004    // [64][128] (render: reduction buffer)
#define OFF_HB    18196    // [64][128] (stage area; render: warp totals)
#define OFF_SIG   26388    // [128] per-point sigma
#define SM_FLOATS 26516
#define SM_BYTES  (SM_FLOATS*4)

extern __shared__ float sm[];

typedef unsigned long long u64;
#define FULLMASK 0xffffffffu

__device__ __forceinline__ u64 pack2(float x, float y) {
    u64 d;
    asm("mov.b64 %0, {%1, %2};" : "=l"(d) : "f"(x), "f"(y));
    return d;
}
__device__ __forceinline__ u64 fma2(u64 a, u64 b, u64 c) {
    u64 d;
    asm("fma.rn.f32x2 %0, %1, %2, %3;" : "=l"(d) : "l"(a), "l"(b), "l"(c));
    return d;
}
__device__ __forceinline__ float2 unpack2(u64 v) {
    float2 r;
    asm("mov.b64 {%0, %1}, %2;" : "=f"(r.x), "=f"(r.y) : "l"(v));
    return r;
}

__device__ __forceinline__ float softplus100(float z) {
    float a = 100.0f * z;
    float sp = fmaxf(a, 0.0f) + __logf(1.0f + __expf(-fabsf(a)));
    return 0.01f * sp;
}

// Tile: 4 points x 16 units per thread. Warp shares one unit group ->
// weight LDS are warp-broadcast, consumed as packed u64 pairs.
// MODE 0: softplus100(acc+b); 1: relu(acc+b);
// 2: dz1 = acc * (1 - exp(-100*h_prev)), h_prev read from Hout.
template<int K, int MODE>
__device__ __forceinline__ void gemm128(const float* __restrict__ Wt,
                                        const float* __restrict__ Hin,
                                        float* __restrict__ Hout,
                                        const float* __restrict__ bias,
                                        int tt)
{
    const int pt0 = (tt & 31) * 4;
    const int u0  = (tt >> 5) * 16;
    u64 acc[4][8];
    #pragma unroll
    for (int i = 0; i < 4; i++)
        #pragma unroll
        for (int j = 0; j < 8; j++) acc[i][j] = 0ull;

    #pragma unroll 8
    for (int k = 0; k < K; k++) {
        float4 av = *(const float4*)&Hin[k*BP + pt0];
        u64 a[4] = {pack2(av.x, av.x), pack2(av.y, av.y),
                    pack2(av.z, av.z), pack2(av.w, av.w)};
        const ulonglong2* wp = (const ulonglong2*)&Wt[k*64 + u0];
        ulonglong2 W01 = wp[0], W23 = wp[1], W45 = wp[2], W67 = wp[3];
        u64 w[8] = {W01.x, W01.y, W23.x, W23.y, W45.x, W45.y, W67.x, W67.y};
        #pragma unroll
        for (int i = 0; i < 4; i++)
            #pragma unroll
            for (int j = 0; j < 8; j++)
                acc[i][j] = fma2(a[i], w[j], acc[i][j]);
    }

    float4 bi[4];
    if (MODE != 2) {
        #pragma unroll
        for (int q = 0; q < 4; q++) bi[q] = *(const float4*)&bias[u0 + 4*q];
    }
    const float* bs = (const float*)bi;

    #pragma unroll
    for (int j = 0; j < 8; j++) {
        float2 r0 = unpack2(acc[0][j]);
        float2 r1 = unpack2(acc[1][j]);
        float2 r2 = unpack2(acc[2][j]);
        float2 r3 = unpack2(acc[3][j]);
        #pragma unroll
        for (int b = 0; b < 2; b++) {
            const int u = u0 + 2*j + b;
            float z0 = b ? r0.y : r0.x;
            float z1 = b ? r1.y : r1.x;
            float z2 = b ? r2.y : r2.x;
            float z3 = b ? r3.y : r3.x;
            float* orow = &Hout[u*BP + pt0];
            float res0, res1, res2, res3;
            if (MODE == 2) {
                float4 vin = *(const float4*)orow;
                res0 = z0 * (1.0f - __expf(-100.0f * vin.x));
                res1 = z1 * (1.0f - __expf(-100.0f * vin.y));
                res2 = z2 * (1.0f - __expf(-100.0f * vin.z));
                res3 = z3 * (1.0f - __expf(-100.0f * vin.w));
            } else {
                float bj = bs[2*j + b];
                if (MODE == 0) {
                    res0 = softplus100(z0 + bj);
                    res1 = softplus100(z1 + bj);
                    res2 = softplus100(z2 + bj);
                    res3 = softplus100(z3 + bj);
                } else {
                    res0 = fmaxf(z0 + bj, 0.0f);
                    res1 = fmaxf(z1 + bj, 0.0f);
                    res2 = fmaxf(z2 + bj, 0.0f);
                    res3 = fmaxf(z3 + bj, 0.0f);
                }
            }
            *(float4*)orow = make_float4(res0, res1, res2, res3);
        }
    }
}

__global__ void __launch_bounds__(NT)
points_kernel(const float* __restrict__ rays_o,
              const float* __restrict__ rays_d,
              const float* __restrict__ rays_d_norm,
              const float* __restrict__ grid,
              const float* __restrict__ w1, const float* __restrict__ b1,
              const float* __restrict__ w2, const float* __restrict__ b2,
              const float* __restrict__ w3, const float* __restrict__ b3,
              const float* __restrict__ cw1, const float* __restrict__ cb1,
              const float* __restrict__ cw2, const float* __restrict__ cb2,
              const float* __restrict__ cw3, const float* __restrict__ cb3,
              const float* __restrict__ beta,
              const int* __restrict__ nearp,
              const int* __restrict__ farp,
              float* __restrict__ out)
{
    const int tt = threadIdx.x;
    const int p  = blockIdx.x * BP + tt;
    const int r  = p >> 6;
    const int s  = p & 63;

    // ---------- phase 0a: weight loads + stage + gather ----------
    for (int t = tt; t < 1024; t += NT) { int i = t >> 6, j = t & 63; sm[OFF_W1T + t] = w1[j*16 + i]; }
    for (int t = tt; t < 1024; t += NT) sm[OFF_W1 + t] = w1[t];
    for (int t = tt; t < 1024; t += NT) { int k = t >> 4, i = t & 15; sm[OFF_W3T + t] = w3[i*64 + k]; }
    for (int t = tt; t < 64; t += NT) {
        sm[OFF_B1 + t] = b1[t]; sm[OFF_B2 + t] = b2[t];
        sm[OFF_CB1 + t] = cb1[t]; sm[OFF_CB2 + t] = cb2[t];
    }
    if (tt < 16) sm[OFF_B3 + tt] = b3[tt];
    if (tt < 4)  sm[OFF_CB3 + tt] = (tt < 3) ? cb3[tt] : 0.0f;
    for (int t = tt; t < 256; t += NT) { int k = t >> 2, i = t & 3; sm[OFF_CW3T + t] = (i < 3) ? cw3[i*64 + k] : 0.0f; }
    // stage w2 coalesced with pitch 65 (for transpose into Wt2)
    for (int t = tt; t < 4096; t += NT) { int j = t >> 6, k = t & 63; sm[OFF_HB + j*65 + k] = w2[t]; }

    // ---- per-point setup + trilinear gather (all 8 corners, this thread) ----
    float nearf = (float)nearp[0];
    float farf  = (float)farp[0];
    float dt    = (farf - nearf) * (1.0f / (float)SAMP);
    float tmid  = nearf + ((float)s + 0.5f) * dt;

    float f[3]; int i0[3]; bool inb[3];
    #pragma unroll
    for (int c = 0; c < 3; c++) {
        float o = rays_o[3*r + c];
        float d = rays_d[3*r + c];
        float xcc = __fadd_rn(o, __fmul_rn(tmid, d));
        float graw = __fmul_rn(__fmul_rn(__fadd_rn(__fdiv_rn(xcc, 1.3f), 1.0f), 0.5f), 127.0f);
        inb[c] = (graw >= 0.0f) && (graw <= 127.0f);
        float gg = fminf(fmaxf(graw, 0.0f), 127.0f);
        int ii = (int)floorf(gg);
        if (ii > 126) ii = 126;
        i0[c] = ii;
        f[c] = gg - (float)ii;
    }
    const bool mask = inb[0] && inb[1] && inb[2];
    const int base000 = (i0[0]*GS + i0[1])*GS + i0[2];

    {
        float wx[2] = {1.0f - f[0], f[0]};
        float wy[2] = {1.0f - f[1], f[1]};
        float wz[2] = {1.0f - f[2], f[2]};
        float emb[EE];
        #pragma unroll
        for (int i = 0; i < EE; i++) emb[i] = 0.0f;
        #pragma unroll
        for (int c = 0; c < 8; c++) {
            const int dx = (c >> 2) & 1, dy = (c >> 1) & 1, dz = c & 1;
            const float w = wx[dx] * wy[dy] * wz[dz];
            const float4* cp = reinterpret_cast<const float4*>(
                grid + (size_t)(base000 + dx*(GS*GS) + dy*GS + dz) * EE);
            #pragma unroll
            for (int q = 0; q < 4; q++) {
                float4 v = cp[q];
                emb[4*q+0] = fmaf(w, v.x, emb[4*q+0]);
                emb[4*q+1] = fmaf(w, v.y, emb[4*q+1]);
                emb[4*q+2] = fmaf(w, v.z, emb[4*q+2]);
                emb[4*q+3] = fmaf(w, v.w, emb[4*q+3]);
            }
        }
        #pragma unroll
        for (int i = 0; i < EE; i++) sm[OFF_F + i*BP + tt] = emb[i];
    }
    __syncthreads();

    // ---------- phase 0b: transpose Wt2 + L1 fwd GEMM ----------
    for (int t = tt; t < 4096; t += NT) { int k = t >> 6, j = t & 63; sm[OFF_WBIG + k*64 + j] = sm[OFF_HB + j*65 + k]; }
    gemm128<16, 0>(sm + OFF_W1T, sm + OFF_F, sm + OFF_HA, sm + OFF_B1, tt);
    __syncthreads();

    // ---------- phase 2: L2 fwd GEMM ----------
    gemm128<64, 0>(sm + OFF_WBIG, sm + OFF_HA, sm + OFF_HB, sm + OFF_B2, tt);
    __syncthreads();

    // ---------- phase 3: load W2 (bwd layout) + L3 fwd (packed) + dz2 + sigma ----------
    for (int t = tt; t < 4096; t += NT) sm[OFF_WBIG + t] = w2[t];
    {
        u64 op[8];
        #pragma unroll
        for (int i = 0; i < 8; i++) op[i] = 0ull;
        #pragma unroll 8
        for (int k = 0; k < 64; k++) {
            float h2k = sm[OFF_HB + k*BP + tt];
            u64 ak = pack2(h2k, h2k);
            const ulonglong2* wr = reinterpret_cast<const ulonglong2*>(&sm[OFF_W3T + k*16]);
            ulonglong2 W0 = wr[0], W1v = wr[1];
            op[0] = fma2(ak, W0.x, op[0]);
            op[1] = fma2(ak, W0.y, op[1]);
            op[2] = fma2(ak, W1v.x, op[2]);
            op[3] = fma2(ak, W1v.y, op[3]);
            ulonglong2 W2v = wr[2], W3v = wr[3];
            op[4] = fma2(ak, W2v.x, op[4]);
            op[5] = fma2(ak, W2v.y, op[5]);
            op[6] = fma2(ak, W3v.x, op[6]);
            op[7] = fma2(ak, W3v.y, op[7]);
            float dz2 = sm[OFF_W3T + k*16 + 0] * (1.0f - __expf(-100.0f * h2k));
            sm[OFF_HB + k*BP + tt] = dz2;
        }
        float o[16];
        #pragma unroll
        for (int i2 = 0; i2 < 8; i2++) {
            float2 v = unpack2(op[i2]);
            o[2*i2+0] = v.x;
            o[2*i2+1] = v.y;
        }
        float sdf = o[0] + sm[OFF_B3 + 0];
        #pragma unroll
        for (int i = 1; i < 16; i++) sm[OFF_F + (i-1)*BP + tt] = o[i] + sm[OFF_B3 + i];
        // Laplace-CDF sigma -> smem (consumed by fused render)
        float be  = 0.015f + fabsf(beta[0]);
        float as  = fabsf(sdf);
        float em1 = __expf(-as / be) - 1.0f;
        float sgn = (sdf > 0.0f) ? 1.0f : ((sdf < 0.0f) ? -1.0f : 0.0f);
        float sg  = (0.5f + 0.5f * sgn * em1) / be;
        sm[OFF_SIG + tt] = mask ? sg : 0.0f;
    }
    __syncthreads();

    // ---------- phase 4: L2 bwd GEMM (dz1 into HA) ----------
    gemm128<64, 2>(sm + OFF_WBIG, sm + OFF_HB, sm + OFF_HA, sm + OFF_B1, tt);
    __syncthreads();

    // ---------- phase 5: load CW1t + stage cw2 + d_emb (packed) + trilinear bwd ----------
    for (int t = tt; t < 18*64; t += NT) { int i = t >> 6, j = t & 63; sm[OFF_WBIG + t] = cw1[j*CIN + i]; }
    for (int t = tt; t < 4096; t += NT) { int j = t >> 6, k = t & 63; sm[OFF_HB + j*65 + k] = cw2[t]; }
    {
        u64 op[8];
        #pragma unroll
        for (int i = 0; i < 8; i++) op[i] = 0ull;
        #pragma unroll 8
        for (int j = 0; j < 64; j++) {
            float d = sm[OFF_HA + j*BP + tt];
            u64 ak = pack2(d, d);
            const ulonglong2* wr = reinterpret_cast<const ulonglong2*>(&sm[OFF_W1 + j*16]);
            ulonglong2 W0 = wr[0], W1v = wr[1];
            op[0] = fma2(ak, W0.x, op[0]);
            op[1] = fma2(ak, W0.y, op[1]);
            op[2] = fma2(ak, W1v.x, op[2]);
            op[3] = fma2(ak, W1v.y, op[3]);
            ulonglong2 W2v = wr[2], W3v = wr[3];
            op[4] = fma2(ak, W2v.x, op[4]);
            op[5] = fma2(ak, W2v.y, op[5]);
            op[6] = fma2(ak, W3v.x, op[6]);
            op[7] = fma2(ak, W3v.y, op[7]);
        }
        float o[16];
        #pragma unroll
        for (int i2 = 0; i2 < 8; i2++) {
            float2 v = unpack2(op[i2]);
            o[2*i2+0] = v.x;
            o[2*i2+1] = v.y;
        }
        // trilinear backward: re-gather corners, dot with o (=d_emb)
        float wx[2] = {1.0f - f[0], f[0]};
        float wy[2] = {1.0f - f[1], f[1]};
        float wz[2] = {1.0f - f[2], f[2]};
        float gx = 0.0f, gy = 0.0f, gz = 0.0f;
        #pragma unroll
        for (int c = 0; c < 8; c++) {
            const int dx = (c >> 2) & 1, dy = (c >> 1) & 1, dz = c & 1;
            const float4* cp = reinterpret_cast<const float4*>(
                grid + (size_t)(base000 + dx*(GS*GS) + dy*GS + dz) * EE);
            float dot = 0.0f;
            #pragma unroll
            for (int q = 0; q < 4; q++) {
                float4 v = cp[q];
                dot = fmaf(o[4*q+0], v.x, dot);
                dot = fmaf(o[4*q+1], v.y, dot);
                dot = fmaf(o[4*q+2], v.z, dot);
                dot = fmaf(o[4*q+3], v.w, dot);
            }
            float sx = dx ? 1.0f : -1.0f;
            float sy = dy ? 1.0f : -1.0f;
            float sz = dz ? 1.0f : -1.0f;
            gx = fmaf(sx * wy[dy] * wz[dz], dot, gx);
            gy = fmaf(wx[dx] * sy * wz[dz], dot, gy);
            gz = fmaf(wx[dx] * wy[dy] * sz, dot, gz);
        }
        const float K = 48.846153846153847f;   // 0.5*(G-1)/BOUND
        float dX = gx * (inb[0] ? K : 0.0f);
        float dY = gy * (inb[1] ? K : 0.0f);
        float dZ = gz * (inb[2] ? K : 0.0f);
        out[RAYS*8 + 3*p + 0] = dX;
        out[RAYS*8 + 3*p + 1] = dY;
        out[RAYS*8 + 3*p + 2] = dZ;
        float nn  = fmaxf(sqrtf(dX*dX + dY*dY + dZ*dZ), 1e-12f);
        float inv = 1.0f / nn;
        sm[OFF_F + 15*BP + tt] = dX * inv;
        sm[OFF_F + 16*BP + tt] = dY * inv;
        sm[OFF_F + 17*BP + tt] = dZ * inv;
    }
    __syncthreads();

    // ---------- phase 6: color L1 GEMM ----------
    gemm128<18, 1>(sm + OFF_WBIG, sm + OFF_F, sm + OFF_HA, sm + OFF_CB1, tt);
    __syncthreads();

    // ---------- phase 7: transpose CWt2 ----------
    for (int t = tt; t < 4096; t += NT) { int k = t >> 6, j = t & 63; sm[OFF_WBIG + k*64 + j] = sm[OFF_HB + j*65 + k]; }
    __syncthreads();

    // ---------- phase 8: color L2 GEMM ----------
    gemm128<64, 1>(sm + OFF_WBIG, sm + OFF_HA, sm + OFF_HB, sm + OFF_CB2, tt);
    __syncthreads();

    // ---------- phase 9: color L3 -> rgb in registers ----------
    float rgb0, rgb1, rgb2;
    {
        float a0 = 0.0f, a1 = 0.0f, a2 = 0.0f;
        #pragma unroll 8
        for (int k = 0; k < 64; k++) {
            float hk = sm[OFF_HB + k*BP + tt];
            float4 cw = *(const float4*)&sm[OFF_CW3T + k*4];
            a0 = fmaf(hk, cw.x, a0);
            a1 = fmaf(hk, cw.y, a1);
            a2 = fmaf(hk, cw.z, a2);
        }
        a0 += sm[OFF_CB3 + 0];
        a1 += sm[OFF_CB3 + 1];
        a2 += sm[OFF_CB3 + 2];
        rgb0 = 1.0f / (1.0f + __expf(-a0));
        rgb1 = 1.0f / (1.0f + __expf(-a1));
        rgb2 = 1.0f / (1.0f + __expf(-a2));
    }
    __syncthreads();   // HB reads done; safe to reuse HA/HB for render

    // ---------- phase 10: fused render (2 rays per block) ----------
    {
        const int rr   = tt >> 6;    // local ray 0/1
        const int ss   = tt & 63;    // sample (== s)
        const int lane = tt & 31;
        const int wid  = tt >> 5;    // warps {0,1}=ray0, {2,3}=ray1

        float dd = sm[OFF_SIG + tt] * dt;
        float cs = dd;
        #pragma unroll
        for (int o = 1; o < 32; o <<= 1) {
            float v = __shfl_up_sync(FULLMASK, cs, o);
            if (lane >= o) cs += v;
        }
        if (lane == 31) sm[OFF_HB + wid] = cs;
        __syncthreads();
        if (wid & 1) cs += sm[OFF_HB + wid - 1];

        float T = __expf(-(cs - dd));      // exclusive prefix
        float w = (1.0f - __expf(-dd)) * T;

        float nx = sm[OFF_F + 15*BP + tt];
        float ny = sm[OFF_F + 16*BP + tt];
        float nz = sm[OFF_F + 17*BP + tt];

        float* red = sm + OFF_HA;
        red[tt*8 + 0] = w * rgb0;
        red[tt*8 + 1] = w * rgb1;
        red[tt*8 + 2] = w * rgb2;
        red[tt*8 + 3] = w * tmid;
        red[tt*8 + 4] = w * nx;
        red[tt*8 + 5] = w * ny;
        red[tt*8 + 6] = w * nz;
        red[tt*8 + 7] = w;
        __syncthreads();

        #pragma unroll
        for (int stride = 32; stride >= 1; stride >>= 1) {
            if (ss < stride) {
                float* a = &red[(rr*64 + ss)*8];
                float* b = &red[(rr*64 + ss + stride)*8];
                float4 a0 = *(float4*)a,       a1 = *(float4*)(a + 4);
                float4 b0 = *(float4*)b,       b1 = *(float4*)(b + 4);
                a0.x += b0.x; a0.y += b0.y; a0.z += b0.z; a0.w += b0.w;
                a1.x += b1.x; a1.y += b1.y; a1.z += b1.z; a1.w += b1.w;
                *(float4*)a = a0;
                *(float4*)(a + 4) = a1;
            }
            __syncthreads();
        }

        if (ss == 0) {
            const int rg = blockIdx.x * 2 + rr;
            float ir = 1.0f / rays_d_norm[rg];
            const float* rb = &red[(rr*64)*8];
            out[8*rg + 0] = rb[0];
            out[8*rg + 1] = rb[1];
            out[8*rg + 2] = rb[2];
            out[8*rg + 3] = rb[3] * ir;
            out[8*rg + 4] = rb[4];
            out[8*rg + 5] = rb[5];
            out[8*rg + 6] = rb[6];
            out[8*rg + 7] = rb[7];
        }
    }
}

extern "C" void kernel_launch(void* const* d_in, const int* in_sizes, int n_in,
                              void* d_out, int out_size)
{
    const float* rays_o      = (const float*)d_in[0];
    const float* rays_d      = (const float*)d_in[1];
    const float* rays_d_norm = (const float*)d_in[2];
    const float* grid        = (const float*)d_in[3];
    const float* sw1 = (const float*)d_in[4];
    const float* sb1 = (const float*)d_in[5];
    const float* sw2 = (const float*)d_in[6];
    const float* sb2 = (const float*)d_in[7];
    const float* sw3 = (const float*)d_in[8];
    const float* sb3 = (const float*)d_in[9];
    const float* cw1 = (const float*)d_in[10];
    const float* cb1 = (const float*)d_in[11];
    const float* cw2 = (const float*)d_in[12];
    const float* cb2 = (const float*)d_in[13];
    const float* cw3 = (const float*)d_in[14];
    const float* cb3 = (const float*)d_in[15];
    const float* beta  = (const float*)d_in[16];
    const int*   nearp = (const int*)d_in[17];
    const int*   farp  = (const int*)d_in[18];
    float* out = (float*)d_out;

    cudaFuncSetAttribute(points_kernel,
                         cudaFuncAttributeMaxDynamicSharedMemorySize, SM_BYTES);

    points_kernel<<<NP/BP, NT, SM_BYTES>>>(rays_o, rays_d, rays_d_norm, grid,
                                           sw1, sb1, sw2, sb2, sw3, sb3,
                                           cw1, cb1, cw2, cb2, cw3, cb3,
                                           beta, nearp, farp, out);
}

// round 12
// speedup vs baseline: 1.1806x; 1.1029x over previous
#include <cuda_runtime.h>

#define RAYS 16384
#define SAMP 64
#define NP (RAYS*SAMP)
#define GS 128
#define EE 16
#define HH 64
#define CIN 18
#define BP 128            // points per block
#define NT 128            // threads per block

// Scratch (device globals; no allocation allowed)
__device__ float g_rgb[NP*3];
__device__ float g_sigma[NP];

// ---- dynamic smem float offsets ----
#define OFF_W1T   0        // [16][64]
#define OFF_W1    1024     // [64][16]
#define OFF_W3T   2048     // [64][16]
#define OFF_B1    3072
#define OFF_B2    3136
#define OFF_B3    3200
#define OFF_CB1   3216
#define OFF_CB2   3280
#define OFF_CB3   3344
#define OFF_CW3T  3348     // [64][4]
#define OFF_WBIG  3604     // [64][64]  Wt2 -> W2 -> CW1t -> CWt2
#define OFF_F     7700     // [18][128]
#define OFF_HA    10004    // [64][128]
#define OFF_HB    18196    // [64][128] (also 64x65 stage area)
#define SM_FLOATS 26388
#define SM_BYTES  (SM_FLOATS*4)

extern __shared__ float sm[];

typedef unsigned long long u64;
#define FULLMASK 0xffffffffu

__device__ __forceinline__ u64 pack2(float x, float y) {
    u64 d;
    asm("mov.b64 %0, {%1, %2};" : "=l"(d) : "f"(x), "f"(y));
    return d;
}
__device__ __forceinline__ u64 fma2(u64 a, u64 b, u64 c) {
    u64 d;
    asm("fma.rn.f32x2 %0, %1, %2, %3;" : "=l"(d) : "l"(a), "l"(b), "l"(c));
    return d;
}
__device__ __forceinline__ float2 unpack2(u64 v) {
    float2 r;
    asm("mov.b64 {%0, %1}, %2;" : "=f"(r.x), "=f"(r.y) : "l"(v));
    return r;
}

__device__ __forceinline__ float softplus100(float z) {
    float a = 100.0f * z;
    float sp = fmaxf(a, 0.0f) + __logf(1.0f + __expf(-fabsf(a)));
    return 0.01f * sp;
}

// Tile: 4 points x 16 units per thread. Warp shares one unit group ->
// weight LDS are warp-broadcast, consumed as packed u64 pairs.
// MODE 0: softplus100(acc+b); 1: relu(acc+b);
// 2: dz1 = acc * (1 - exp(-100*h_prev)), h_prev read from Hout.
template<int K, int MODE>
__device__ __forceinline__ void gemm128(const float* __restrict__ Wt,
                                        const float* __restrict__ Hin,
                                        float* __restrict__ Hout,
                                        const float* __restrict__ bias,
                                        int tt)
{
    const int pt0 = (tt & 31) * 4;
    const int u0  = (tt >> 5) * 16;
    u64 acc[4][8];
    #pragma unroll
    for (int i = 0; i < 4; i++)
        #pragma unroll
        for (int j = 0; j < 8; j++) acc[i][j] = 0ull;

    #pragma unroll 8
    for (int k = 0; k < K; k++) {
        float4 av = *(const float4*)&Hin[k*BP + pt0];
        u64 a[4] = {pack2(av.x, av.x), pack2(av.y, av.y),
                    pack2(av.z, av.z), pack2(av.w, av.w)};
        const ulonglong2* wp = (const ulonglong2*)&Wt[k*64 + u0];
        ulonglong2 W01 = wp[0], W23 = wp[1], W45 = wp[2], W67 = wp[3];
        u64 w[8] = {W01.x, W01.y, W23.x, W23.y, W45.x, W45.y, W67.x, W67.y};
        #pragma unroll
        for (int i = 0; i < 4; i++)
            #pragma unroll
            for (int j = 0; j < 8; j++)
                acc[i][j] = fma2(a[i], w[j], acc[i][j]);
    }

    float4 bi[4];
    if (MODE != 2) {
        #pragma unroll
        for (int q = 0; q < 4; q++) bi[q] = *(const float4*)&bias[u0 + 4*q];
    }
    const float* bs = (const float*)bi;

    #pragma unroll
    for (int j = 0; j < 8; j++) {
        float2 r0 = unpack2(acc[0][j]);
        float2 r1 = unpack2(acc[1][j]);
        float2 r2 = unpack2(acc[2][j]);
        float2 r3 = unpack2(acc[3][j]);
        #pragma unroll
        for (int b = 0; b < 2; b++) {
            const int u = u0 + 2*j + b;
            float z0 = b ? r0.y : r0.x;
            float z1 = b ? r1.y : r1.x;
            float z2 = b ? r2.y : r2.x;
            float z3 = b ? r3.y : r3.x;
            float* orow = &Hout[u*BP + pt0];
            float res0, res1, res2, res3;
            if (MODE == 2) {
                float4 vin = *(const float4*)orow;
                res0 = z0 * (1.0f - __expf(-100.0f * vin.x));
                res1 = z1 * (1.0f - __expf(-100.0f * vin.y));
                res2 = z2 * (1.0f - __expf(-100.0f * vin.z));
                res3 = z3 * (1.0f - __expf(-100.0f * vin.w));
            } else {
                float bj = bs[2*j + b];
                if (MODE == 0) {
                    res0 = softplus100(z0 + bj);
                    res1 = softplus100(z1 + bj);
                    res2 = softplus100(z2 + bj);
                    res3 = softplus100(z3 + bj);
                } else {
                    res0 = fmaxf(z0 + bj, 0.0f);
                    res1 = fmaxf(z1 + bj, 0.0f);
                    res2 = fmaxf(z2 + bj, 0.0f);
                    res3 = fmaxf(z3 + bj, 0.0f);
                }
            }
            *(float4*)orow = make_float4(res0, res1, res2, res3);
        }
    }
}

__global__ void __launch_bounds__(NT)
points_kernel(const float* __restrict__ rays_o,
              const float* __restrict__ rays_d,
              const float* __restrict__ grid,
              const float* __restrict__ w1, const float* __restrict__ b1,
              const float* __restrict__ w2, const float* __restrict__ b2,
              const float* __restrict__ w3, const float* __restrict__ b3,
              const float* __restrict__ cw1, const float* __restrict__ cb1,
              const float* __restrict__ cw2, const float* __restrict__ cb2,
              const float* __restrict__ cw3, const float* __restrict__ cb3,
              const float* __restrict__ beta,
              const int* __restrict__ nearp,
              const int* __restrict__ farp,
              float* __restrict__ out)
{
    const int tt = threadIdx.x;
    const int p  = blockIdx.x * BP + tt;
    const int r  = p >> 6;
    const int s  = p & 63;

    // ---------- phase 0a: weight loads + stage + gather ----------
    for (int t = tt; t < 1024; t += NT) { int i = t >> 6, j = t & 63; sm[OFF_W1T + t] = w1[j*16 + i]; }
    #pragma unroll
    for (int q = 0; q < 2; q++) {
        int t4 = q*128 + tt;
        *(float4*)&sm[OFF_W1 + t4*4] = ((const float4*)w1)[t4];
    }
    for (int t = tt; t < 1024; t += NT) { int k = t >> 4, i = t & 15; sm[OFF_W3T + t] = w3[i*64 + k]; }
    for (int t = tt; t < 64; t += NT) {
        sm[OFF_B1 + t] = b1[t]; sm[OFF_B2 + t] = b2[t];
        sm[OFF_CB1 + t] = cb1[t]; sm[OFF_CB2 + t] = cb2[t];
    }
    if (tt < 16) sm[OFF_B3 + tt] = b3[tt];
    if (tt < 4)  sm[OFF_CB3 + tt] = (tt < 3) ? cb3[tt] : 0.0f;
    for (int t = tt; t < 256; t += NT) { int k = t >> 2, i = t & 3; sm[OFF_CW3T + t] = (i < 3) ? cw3[i*64 + k] : 0.0f; }
    // stage w2 with pitch 65 (for conflict-free transpose into Wt2); float4 LDG
    {
        const float4* w2v4 = (const float4*)w2;
        #pragma unroll
        for (int q = 0; q < 8; q++) {
            int t4 = q*128 + tt;
            float4 v = w2v4[t4];
            int j = t4 >> 4, k4 = t4 & 15;
            float* dst = &sm[OFF_HB + j*65 + 4*k4];
            dst[0] = v.x; dst[1] = v.y; dst[2] = v.z; dst[3] = v.w;
        }
    }

    // ---- per-point setup + trilinear gather (all 8 corners, this thread) ----
    float nearf = (float)nearp[0];
    float farf  = (float)farp[0];
    float dt    = (farf - nearf) * (1.0f / (float)SAMP);
    float tmid  = nearf + ((float)s + 0.5f) * dt;

    float f[3]; int i0[3]; bool inb[3];
    #pragma unroll
    for (int c = 0; c < 3; c++) {
        float o = rays_o[3*r + c];
        float d = rays_d[3*r + c];
        float xcc = __fadd_rn(o, __fmul_rn(tmid, d));
        float graw = __fmul_rn(__fmul_rn(__fadd_rn(__fdiv_rn(xcc, 1.3f), 1.0f), 0.5f), 127.0f);
        inb[c] = (graw >= 0.0f) && (graw <= 127.0f);
        float gg = fminf(fmaxf(graw, 0.0f), 127.0f);
        int ii = (int)floorf(gg);
        if (ii > 126) ii = 126;
        i0[c] = ii;
        f[c] = gg - (float)ii;
    }
    const bool mask = inb[0] && inb[1] && inb[2];
    const int base000 = (i0[0]*GS + i0[1])*GS + i0[2];

    {
        float wx[2] = {1.0f - f[0], f[0]};
        float wy[2] = {1.0f - f[1], f[1]};
        float wz[2] = {1.0f - f[2], f[2]};
        float emb[EE];
        #pragma unroll
        for (int i = 0; i < EE; i++) emb[i] = 0.0f;
        #pragma unroll
        for (int c = 0; c < 8; c++) {
            const int dx = (c >> 2) & 1, dy = (c >> 1) & 1, dz = c & 1;
            const float w = wx[dx] * wy[dy] * wz[dz];
            const float4* cp = reinterpret_cast<const float4*>(
                grid + (size_t)(base000 + dx*(GS*GS) + dy*GS + dz) * EE);
            #pragma unroll
            for (int q = 0; q < 4; q++) {
                float4 v = cp[q];
                emb[4*q+0] = fmaf(w, v.x, emb[4*q+0]);
                emb[4*q+1] = fmaf(w, v.y, emb[4*q+1]);
                emb[4*q+2] = fmaf(w, v.z, emb[4*q+2]);
                emb[4*q+3] = fmaf(w, v.w, emb[4*q+3]);
            }
        }
        #pragma unroll
        for (int i = 0; i < EE; i++) sm[OFF_F + i*BP + tt] = emb[i];
    }
    __syncthreads();

    // ---------- phase 0b: transpose Wt2 + L1 fwd GEMM ----------
    for (int t = tt; t < 4096; t += NT) { int k = t >> 6, j = t & 63; sm[OFF_WBIG + k*64 + j] = sm[OFF_HB + j*65 + k]; }
    gemm128<16, 0>(sm + OFF_W1T, sm + OFF_F, sm + OFF_HA, sm + OFF_B1, tt);
    __syncthreads();

    // ---------- phase 2: L2 fwd GEMM (+ prefetch W2 row-major for phase 3) ----------
    gemm128<64, 0>(sm + OFF_WBIG, sm + OFF_HA, sm + OFF_HB, sm + OFF_B2, tt);
    float4 pw[8];
    {
        const float4* w2v = (const float4*)w2;
        #pragma unroll
        for (int q = 0; q < 8; q++) pw[q] = w2v[q*128 + tt];
    }
    __syncthreads();

    // ---------- phase 3: store prefetched W2 + L3 fwd (packed) + dz2 + sigma ----------
    #pragma unroll
    for (int q = 0; q < 8; q++) *(float4*)&sm[OFF_WBIG + (q*128 + tt)*4] = pw[q];
    {
        u64 op[8];
        #pragma unroll
        for (int i = 0; i < 8; i++) op[i] = 0ull;
        #pragma unroll 8
        for (int k = 0; k < 64; k++) {
            float h2k = sm[OFF_HB + k*BP + tt];
            u64 ak = pack2(h2k, h2k);
            const ulonglong2* wr = reinterpret_cast<const ulonglong2*>(&sm[OFF_W3T + k*16]);
            ulonglong2 W0 = wr[0], W1v = wr[1];
            op[0] = fma2(ak, W0.x, op[0]);
            op[1] = fma2(ak, W0.y, op[1]);
            op[2] = fma2(ak, W1v.x, op[2]);
            op[3] = fma2(ak, W1v.y, op[3]);
            ulonglong2 W2v = wr[2], W3v = wr[3];
            op[4] = fma2(ak, W2v.x, op[4]);
            op[5] = fma2(ak, W2v.y, op[5]);
            op[6] = fma2(ak, W3v.x, op[6]);
            op[7] = fma2(ak, W3v.y, op[7]);
            float dz2 = sm[OFF_W3T + k*16 + 0] * (1.0f - __expf(-100.0f * h2k));
            sm[OFF_HB + k*BP + tt] = dz2;
        }
        float o[16];
        #pragma unroll
        for (int i2 = 0; i2 < 8; i2++) {
            float2 v = unpack2(op[i2]);
            o[2*i2+0] = v.x;
            o[2*i2+1] = v.y;
        }
        float sdf = o[0] + sm[OFF_B3 + 0];
        #pragma unroll
        for (int i = 1; i < 16; i++) sm[OFF_F + (i-1)*BP + tt] = o[i] + sm[OFF_B3 + i];
        // Laplace-CDF sigma
        float be  = 0.015f + fabsf(beta[0]);
        float as  = fabsf(sdf);
        float em1 = __expf(-as / be) - 1.0f;
        float sgn = (sdf > 0.0f) ? 1.0f : ((sdf < 0.0f) ? -1.0f : 0.0f);
        float sg  = (0.5f + 0.5f * sgn * em1) / be;
        g_sigma[p] = mask ? sg : 0.0f;
    }
    __syncthreads();

    // ---------- phase 4: L2 bwd GEMM (+ prefetch CW1t / cw2 stage for phase 5) ----------
    gemm128<64, 2>(sm + OFF_WBIG, sm + OFF_HB, sm + OFF_HA, sm + OFF_B1, tt);
    float pcw1[9];
    float4 pcw2[8];
    {
        #pragma unroll
        for (int q = 0; q < 9; q++) {
            int t = q*128 + tt;            // t < 1152
            int i = t >> 6, j = t & 63;
            pcw1[q] = cw1[j*CIN + i];
        }
        const float4* cw2v = (const float4*)cw2;
        #pragma unroll
        for (int q = 0; q < 8; q++) pcw2[q] = cw2v[q*128 + tt];
    }
    __syncthreads();

    // ---------- phase 5: store prefetches + d_emb (packed) + trilinear bwd ----------
    #pragma unroll
    for (int q = 0; q < 9; q++) sm[OFF_WBIG + q*128 + tt] = pcw1[q];
    #pragma unroll
    for (int q = 0; q < 8; q++) {
        int t4 = q*128 + tt;
        int j = t4 >> 4, k4 = t4 & 15;
        float* dst = &sm[OFF_HB + j*65 + 4*k4];
        dst[0] = pcw2[q].x; dst[1] = pcw2[q].y; dst[2] = pcw2[q].z; dst[3] = pcw2[q].w;
    }
    {
        u64 op[8];
        #pragma unroll
        for (int i = 0; i < 8; i++) op[i] = 0ull;
        #pragma unroll 8
        for (int j = 0; j < 64; j++) {
            float d = sm[OFF_HA + j*BP + tt];
            u64 ak = pack2(d, d);
            const ulonglong2* wr = reinterpret_cast<const ulonglong2*>(&sm[OFF_W1 + j*16]);
            ulonglong2 W0 = wr[0], W1v = wr[1];
            op[0] = fma2(ak, W0.x, op[0]);
            op[1] = fma2(ak, W0.y, op[1]);
            op[2] = fma2(ak, W1v.x, op[2]);
            op[3] = fma2(ak, W1v.y, op[3]);
            ulonglong2 W2v = wr[2], W3v = wr[3];
            op[4] = fma2(ak, W2v.x, op[4]);
            op[5] = fma2(ak, W2v.y, op[5]);
            op[6] = fma2(ak, W3v.x, op[6]);
            op[7] = fma2(ak, W3v.y, op[7]);
        }
        float o[16];
        #pragma unroll
        for (int i2 = 0; i2 < 8; i2++) {
            float2 v = unpack2(op[i2]);
            o[2*i2+0] = v.x;
            o[2*i2+1] = v.y;
        }
        // trilinear backward: re-gather corners, dot with o (=d_emb)
        float wx[2] = {1.0f - f[0], f[0]};
        float wy[2] = {1.0f - f[1], f[1]};
        float wz[2] = {1.0f - f[2], f[2]};
        float gx = 0.0f, gy = 0.0f, gz = 0.0f;
        #pragma unroll
        for (int c = 0; c < 8; c++) {
            const int dx = (c >> 2) & 1, dy = (c >> 1) & 1, dz = c & 1;
            const float4* cp = reinterpret_cast<const float4*>(
                grid + (size_t)(base000 + dx*(GS*GS) + dy*GS + dz) * EE);
            float dot = 0.0f;
            #pragma unroll
            for (int q = 0; q < 4; q++) {
                float4 v = cp[q];
                dot = fmaf(o[4*q+0], v.x, dot);
                dot = fmaf(o[4*q+1], v.y, dot);
                dot = fmaf(o[4*q+2], v.z, dot);
                dot = fmaf(o[4*q+3], v.w, dot);
            }
            float sx = dx ? 1.0f : -1.0f;
            float sy = dy ? 1.0f : -1.0f;
            float sz = dz ? 1.0f : -1.0f;
            gx = fmaf(sx * wy[dy] * wz[dz], dot, gx);
            gy = fmaf(wx[dx] * sy * wz[dz], dot, gy);
            gz = fmaf(wx[dx] * wy[dy] * sz, dot, gz);
        }
        const float K = 48.846153846153847f;   // 0.5*(G-1)/BOUND
        float dX = gx * (inb[0] ? K : 0.0f);
        float dY = gy * (inb[1] ? K : 0.0f);
        float dZ = gz * (inb[2] ? K : 0.0f);
        out[RAYS*8 + 3*p + 0] = dX;
        out[RAYS*8 + 3*p + 1] = dY;
        out[RAYS*8 + 3*p + 2] = dZ;
        float nn  = fmaxf(sqrtf(dX*dX + dY*dY + dZ*dZ), 1e-12f);
        float inv = 1.0f / nn;
        sm[OFF_F + 15*BP + tt] = dX * inv;
        sm[OFF_F + 16*BP + tt] = dY * inv;
        sm[OFF_F + 17*BP + tt] = dZ * inv;
    }
    __syncthreads();

    // ---------- phase 6: color L1 GEMM ----------
    gemm128<18, 1>(sm + OFF_WBIG, sm + OFF_F, sm + OFF_HA, sm + OFF_CB1, tt);
    __syncthreads();

    // ---------- phase 7: transpose CWt2 ----------
    for (int t = tt; t < 4096; t += NT) { int k = t >> 6, j = t & 63; sm[OFF_WBIG + k*64 + j] = sm[OFF_HB + j*65 + k]; }
    __syncthreads();

    // ---------- phase 8: color L2 GEMM ----------
    gemm128<64, 1>(sm + OFF_WBIG, sm + OFF_HA, sm + OFF_HB, sm + OFF_CB2, tt);
    __syncthreads();

    // ---------- phase 9: color L3 (scalar) ----------
    {
        float a0 = 0.0f, a1 = 0.0f, a2 = 0.0f;
        #pragma unroll 8
        for (int k = 0; k < 64; k++) {
            float hk = sm[OFF_HB + k*BP + tt];
            float4 cw = *(const float4*)&sm[OFF_CW3T + k*4];
            a0 = fmaf(hk, cw.x, a0);
            a1 = fmaf(hk, cw.y, a1);
            a2 = fmaf(hk, cw.z, a2);
        }
        a0 += sm[OFF_CB3 + 0];
        a1 += sm[OFF_CB3 + 1];
        a2 += sm[OFF_CB3 + 2];
        g_rgb[3*p + 0] = 1.0f / (1.0f + __expf(-a0));
        g_rgb[3*p + 1] = 1.0f / (1.0f + __expf(-a1));
        g_rgb[3*p + 2] = 1.0f / (1.0f + __expf(-a2));
    }
}

// ---------------- render: 1 block (64 threads) per ray, shfl scan ----------------
__global__ void __launch_bounds__(64)
render_kernel(const float* __restrict__ rays_d_norm,
              const int* __restrict__ nearp, const int* __restrict__ farp,
              float* __restrict__ out)
{
    __shared__ float red[64*8];
    __shared__ float warp0_total;
    const int r = blockIdx.x;
    const int s = threadIdx.x;
    const int lane = s & 31;
    const int wrp  = s >> 5;
    const int p = r * SAMP + s;

    float nearf = (float)nearp[0];
    float farf  = (float)farp[0];
    float dt    = (farf - nearf) * (1.0f / (float)SAMP);
    const float* grads = out + RAYS*8;

    float dd = g_sigma[p] * dt;

    float cs = dd;
    #pragma unroll
    for (int o = 1; o < 32; o <<= 1) {
        float v = __shfl_up_sync(0xffffffffu, cs, o);
        if (lane >= o) cs += v;
    }
    if (wrp == 0 && lane == 31) warp0_total = cs;
    __syncthreads();
    if (wrp == 1) cs += warp0_total;

    float T = __expf(-(cs - dd));
    float w = (1.0f - __expf(-dd)) * T;

    float rgb0 = g_rgb[3*p + 0], rgb1 = g_rgb[3*p + 1], rgb2 = g_rgb[3*p + 2];
    float gx = grads[3*p + 0], gy = grads[3*p + 1], gz = grads[3*p + 2];
    float nn = fmaxf(sqrtf(gx*gx + gy*gy + gz*gz), 1e-12f);
    float wi = w / nn;
    float tm = nearf + ((float)s + 0.5f) * dt;

    red[s*8 + 0] = w * rgb0;
    red[s*8 + 1] = w * rgb1;
    red[s*8 + 2] = w * rgb2;
    red[s*8 + 3] = w * tm;
    red[s*8 + 4] = wi * gx;
    red[s*8 + 5] = wi * gy;
    red[s*8 + 6] = wi * gz;
    red[s*8 + 7] = w;
    __syncthreads();

    #pragma unroll
    for (int stride = 32; stride >= 1; stride >>= 1) {
        if (s < stride) {
            float4 a0 = *(float4*)&red[s*8];
            float4 a1 = *(float4*)&red[s*8 + 4];
            float4 b0 = *(float4*)&red[(s+stride)*8];
            float4 b1 = *(float4*)&red[(s+stride)*8 + 4];
            a0.x += b0.x; a0.y += b0.y; a0.z += b0.z; a0.w += b0.w;
            a1.x += b1.x; a1.y += b1.y; a1.z += b1.z; a1.w += b1.w;
            *(float4*)&red[s*8] = a0;
            *(float4*)&red[s*8 + 4] = a1;
        }
        __syncthreads();
    }

    if (s == 0) {
        float ir = 1.0f / rays_d_norm[r];
        out[8*r + 0] = red[0];
        out[8*r + 1] = red[1];
        out[8*r + 2] = red[2];
        out[8*r + 3] = red[3] * ir;
        out[8*r + 4] = red[4];
        out[8*r + 5] = red[5];
        out[8*r + 6] = red[6];
        out[8*r + 7] = red[7];
    }
}

extern "C" void kernel_launch(void* const* d_in, const int* in_sizes, int n_in,
                              void* d_out, int out_size)
{
    const float* rays_o      = (const float*)d_in[0];
    const float* rays_d      = (const float*)d_in[1];
    const float* rays_d_norm = (const float*)d_in[2];
    const float* grid        = (const float*)d_in[3];
    const float* sw1 = (const float*)d_in[4];
    const float* sb1 = (const float*)d_in[5];
    const float* sw2 = (const float*)d_in[6];
    const float* sb2 = (const float*)d_in[7];
    const float* sw3 = (const float*)d_in[8];
    const float* sb3 = (const float*)d_in[9];
    const float* cw1 = (const float*)d_in[10];
    const float* cb1 = (const float*)d_in[11];
    const float* cw2 = (const float*)d_in[12];
    const float* cb2 = (const float*)d_in[13];
    const float* cw3 = (const float*)d_in[14];
    const float* cb3 = (const float*)d_in[15];
    const float* beta  = (const float*)d_in[16];
    const int*   nearp = (const int*)d_in[17];
    const int*   farp  = (const int*)d_in[18];
    float* out = (float*)d_out;

    cudaFuncSetAttribute(points_kernel,
                         cudaFuncAttributeMaxDynamicSharedMemorySize, SM_BYTES);

    points_kernel<<<NP/BP, NT, SM_BYTES>>>(rays_o, rays_d, grid,
                                           sw1, sb1, sw2, sb2, sw3, sb3,
                                           cw1, cb1, cw2, cb2, cw3, cb3,
                                           beta, nearp, farp, out);
    render_kernel<<<RAYS, 64>>>(rays_d_norm, nearp, farp, out);
}

// round 16
// speedup vs baseline: 1.2258x; 1.0383x over previous
#include <cuda_runtime.h>

#define RAYS 16384
#define SAMP 64
#define NP (RAYS*SAMP)
#define GS 128
#define EE 16
#define HH 64
#define CIN 18
#define BP 256            // points per block
#define NT 256            // threads per block

// Scratch (device globals; no allocation allowed)
__device__ float g_rgb[NP*3];
__device__ float g_sigma[NP];

// ---- dynamic smem float offsets (all 16B-aligned) ----
#define OFF_W1T   0        // [16][64]
#define OFF_W1    1024     // [64][16]
#define OFF_W3T   2048     // [64][16]
#define OFF_B1    3072
#define OFF_B2    3136
#define OFF_B3    3200
#define OFF_CB1   3216
#define OFF_CB2   3280
#define OFF_CB3   3344
#define OFF_CW3T  3348     // [64][4]
#define OFF_CW1T  3604     // [18][64] dedicated (loaded once)
#define OFF_WBIG  4756     // [64][64]  Wt2 -> W2 -> CWt2
#define OFF_F     8852     // [18][256]
#define OFF_HA    13460    // [64][256]
#define OFF_HB    29844    // [64][256] (also 64x65 stage area)
#define SM_FLOATS 46228
#define SM_BYTES  (SM_FLOATS*4)

extern __shared__ float sm[];

typedef unsigned long long u64;
#define FULLMASK 0xffffffffu

__device__ __forceinline__ u64 pack2(float x, float y) {
    u64 d;
    asm("mov.b64 %0, {%1, %2};" : "=l"(d) : "f"(x), "f"(y));
    return d;
}
__device__ __forceinline__ u64 fma2(u64 a, u64 b, u64 c) {
    u64 d;
    asm("fma.rn.f32x2 %0, %1, %2, %3;" : "=l"(d) : "l"(a), "l"(b), "l"(c));
    return d;
}
__device__ __forceinline__ float2 unpack2(u64 v) {
    float2 r;
    asm("mov.b64 {%0, %1}, %2;" : "=f"(r.x), "=f"(r.y) : "l"(v));
    return r;
}

__device__ __forceinline__ float softplus100(float z) {
    float a = 100.0f * z;
    float sp = fmaxf(a, 0.0f) + __logf(1.0f + __expf(-fabsf(a)));
    return 0.01f * sp;
}

// Tile: 4 points x 16 units per thread (256 threads cover 256 pts x 64 units).
// Unit group (tt>>6)*16 is warp-uniform -> weight LDS broadcast, consumed as
// packed u64 pairs. MODE 0: softplus100(acc+b); 1: relu(acc+b);
// 2: dz1 = acc * (1 - exp(-100*h_prev)), h_prev read from Hout.
template<int K, int MODE>
__device__ __forceinline__ void gemm128(const float* __restrict__ Wt,
                                        const float* __restrict__ Hin,
                                        float* __restrict__ Hout,
                                        const float* __restrict__ bias,
                                        int tt)
{
    const int pt0 = (tt & 63) * 4;
    const int u0  = (tt >> 6) * 16;
    u64 acc[4][8];
    #pragma unroll
    for (int i = 0; i < 4; i++)
        #pragma unroll
        for (int j = 0; j < 8; j++) acc[i][j] = 0ull;

    #pragma unroll 8
    for (int k = 0; k < K; k++) {
        float4 av = *(const float4*)&Hin[k*BP + pt0];
        u64 a[4] = {pack2(av.x, av.x), pack2(av.y, av.y),
                    pack2(av.z, av.z), pack2(av.w, av.w)};
        const ulonglong2* wp = (const ulonglong2*)&Wt[k*64 + u0];
        ulonglong2 W01 = wp[0], W23 = wp[1], W45 = wp[2], W67 = wp[3];
        u64 w[8] = {W01.x, W01.y, W23.x, W23.y, W45.x, W45.y, W67.x, W67.y};
        #pragma unroll
        for (int i = 0; i < 4; i++)
            #pragma unroll
            for (int j = 0; j < 8; j++)
                acc[i][j] = fma2(a[i], w[j], acc[i][j]);
    }

    float4 bi[4];
    if (MODE != 2) {
        #pragma unroll
        for (int q = 0; q < 4; q++) bi[q] = *(const float4*)&bias[u0 + 4*q];
    }
    const float* bs = (const float*)bi;

    #pragma unroll
    for (int j = 0; j < 8; j++) {
        float2 r0 = unpack2(acc[0][j]);
        float2 r1 = unpack2(acc[1][j]);
        float2 r2 = unpack2(acc[2][j]);
        float2 r3 = unpack2(acc[3][j]);
        #pragma unroll
        for (int b = 0; b < 2; b++) {
            const int u = u0 + 2*j + b;
            float z0 = b ? r0.y : r0.x;
            float z1 = b ? r1.y : r1.x;
            float z2 = b ? r2.y : r2.x;
            float z3 = b ? r3.y : r3.x;
            float* orow = &Hout[u*BP + pt0];
            float res0, res1, res2, res3;
            if (MODE == 2) {
                float4 vin = *(const float4*)orow;
                res0 = z0 * (1.0f - __expf(-100.0f * vin.x));
                res1 = z1 * (1.0f - __expf(-100.0f * vin.y));
                res2 = z2 * (1.0f - __expf(-100.0f * vin.z));
                res3 = z3 * (1.0f - __expf(-100.0f * vin.w));
            } else {
                float bj = bs[2*j + b];
                if (MODE == 0) {
                    res0 = softplus100(z0 + bj);
                    res1 = softplus100(z1 + bj);
                    res2 = softplus100(z2 + bj);
                    res3 = softplus100(z3 + bj);
                } else {
                    res0 = fmaxf(z0 + bj, 0.0f);
                    res1 = fmaxf(z1 + bj, 0.0f);
                    res2 = fmaxf(z2 + bj, 0.0f);
                    res3 = fmaxf(z3 + bj, 0.0f);
                }
            }
            *(float4*)orow = make_float4(res0, res1, res2, res3);
        }
    }
}

__global__ void __launch_bounds__(NT)
points_kernel(const float* __restrict__ rays_o,
              const float* __restrict__ rays_d,
              const float* __restrict__ grid,
              const float* __restrict__ w1, const float* __restrict__ b1,
              const float* __restrict__ w2, const float* __restrict__ b2,
              const float* __restrict__ w3, const float* __restrict__ b3,
              const float* __restrict__ cw1, const float* __restrict__ cb1,
              const float* __restrict__ cw2, const float* __restrict__ cb2,
              const float* __restrict__ cw3, const float* __restrict__ cb3,
              const float* __restrict__ beta,
              const int* __restrict__ nearp,
              const int* __restrict__ farp,
              float* __restrict__ out)
{
    const int tt = threadIdx.x;
    const int p  = blockIdx.x * BP + tt;
    const int r  = p >> 6;
    const int s  = p & 63;

    // ---------- phase 0a: ALL weight loads (once) + stage + gather ----------
    for (int t = tt; t < 1024; t += NT) { int i = t >> 6, j = t & 63; sm[OFF_W1T + t] = w1[j*16 + i]; }
    *(float4*)&sm[OFF_W1 + tt*4] = ((const float4*)w1)[tt];
    for (int t = tt; t < 1024; t += NT) { int k = t >> 4, i = t & 15; sm[OFF_W3T + t] = w3[i*64 + k]; }
    for (int t = tt; t < 1152; t += NT) { int k = t >> 6, j = t & 63; sm[OFF_CW1T + t] = cw1[j*CIN + k]; }
    if (tt < 64) {
        sm[OFF_B1 + tt] = b1[tt]; sm[OFF_B2 + tt] = b2[tt];
        sm[OFF_CB1 + tt] = cb1[tt]; sm[OFF_CB2 + tt] = cb2[tt];
    }
    if (tt < 16) sm[OFF_B3 + tt] = b3[tt];
    if (tt < 4)  sm[OFF_CB3 + tt] = (tt < 3) ? cb3[tt] : 0.0f;
    if (tt >= 192) { int t = tt - 192 + 0; }  // no-op
    for (int t = tt; t < 256; t += NT) { int k = t >> 2, i = t & 3; sm[OFF_CW3T + t] = (i < 3) ? cw3[i*64 + k] : 0.0f; }
    // stage w2 with pitch 65 (for conflict-free transpose into Wt2); float4 LDG
    {
        const float4* w2v4 = (const float4*)w2;
        #pragma unroll
        for (int q = 0; q < 4; q++) {
            int t4 = q*256 + tt;
            float4 v = w2v4[t4];
            int j = t4 >> 4, k4 = t4 & 15;
            float* dst = &sm[OFF_HB + j*65 + 4*k4];
            dst[0] = v.x; dst[1] = v.y; dst[2] = v.z; dst[3] = v.w;
        }
    }

    // ---- per-point setup + trilinear gather (all 8 corners, this thread) ----
    float nearf = (float)nearp[0];
    float farf  = (float)farp[0];
    float dt    = (farf - nearf) * (1.0f / (float)SAMP);
    float tmid  = nearf + ((float)s + 0.5f) * dt;

    float f[3]; int i0[3]; bool inb[3];
    #pragma unroll
    for (int c = 0; c < 3; c++) {
        float o = rays_o[3*r + c];
        float d = rays_d[3*r + c];
        float xcc = __fadd_rn(o, __fmul_rn(tmid, d));
        float graw = __fmul_rn(__fmul_rn(__fadd_rn(__fdiv_rn(xcc, 1.3f), 1.0f), 0.5f), 127.0f);
        inb[c] = (graw >= 0.0f) && (graw <= 127.0f);
        float gg = fminf(fmaxf(graw, 0.0f), 127.0f);
        int ii = (int)floorf(gg);
        if (ii > 126) ii = 126;
        i0[c] = ii;
        f[c] = gg - (float)ii;
    }
    const bool mask = inb[0] && inb[1] && inb[2];
    const int base000 = (i0[0]*GS + i0[1])*GS + i0[2];

    {
        float wx[2] = {1.0f - f[0], f[0]};
        float wy[2] = {1.0f - f[1], f[1]};
        float wz[2] = {1.0f - f[2], f[2]};
        float emb[EE];
        #pragma unroll
        for (int i = 0; i < EE; i++) emb[i] = 0.0f;
        #pragma unroll
        for (int c = 0; c < 8; c++) {
            const int dx = (c >> 2) & 1, dy = (c >> 1) & 1, dz = c & 1;
            const float w = wx[dx] * wy[dy] * wz[dz];
            const float4* cp = reinterpret_cast<const float4*>(
                grid + (size_t)(base000 + dx*(GS*GS) + dy*GS + dz) * EE);
            #pragma unroll
            for (int q = 0; q < 4; q++) {
                float4 v = cp[q];
                emb[4*q+0] = fmaf(w, v.x, emb[4*q+0]);
                emb[4*q+1] = fmaf(w, v.y, emb[4*q+1]);
                emb[4*q+2] = fmaf(w, v.z, emb[4*q+2]);
                emb[4*q+3] = fmaf(w, v.w, emb[4*q+3]);
            }
        }
        #pragma unroll
        for (int i = 0; i < EE; i++) sm[OFF_F + i*BP + tt] = emb[i];
    }
    __syncthreads();

    // ---------- phase 0b: transpose Wt2 + L1 fwd GEMM ----------
    for (int t = tt; t < 4096; t += NT) { int k = t >> 6, j = t & 63; sm[OFF_WBIG + k*64 + j] = sm[OFF_HB + j*65 + k]; }
    gemm128<16, 0>(sm + OFF_W1T, sm + OFF_F, sm + OFF_HA, sm + OFF_B1, tt);
    __syncthreads();

    // ---------- phase 2: L2 fwd GEMM (+ prefetch W2 row-major for phase 3) ----------
    gemm128<64, 0>(sm + OFF_WBIG, sm + OFF_HA, sm + OFF_HB, sm + OFF_B2, tt);
    float4 pw[4];
    {
        const float4* w2v = (const float4*)w2;
        #pragma unroll
        for (int q = 0; q < 4; q++) pw[q] = w2v[q*256 + tt];
    }
    __syncthreads();

    // ---------- phase 3: store prefetched W2 + L3 fwd (packed) + dz2 + sigma ----------
    #pragma unroll
    for (int q = 0; q < 4; q++) *(float4*)&sm[OFF_WBIG + (q*256 + tt)*4] = pw[q];
    {
        u64 op[8];
        #pragma unroll
        for (int i = 0; i < 8; i++) op[i] = 0ull;
        #pragma unroll 8
        for (int k = 0; k < 64; k++) {
            float h2k = sm[OFF_HB + k*BP + tt];
            u64 ak = pack2(h2k, h2k);
            const ulonglong2* wr = reinterpret_cast<const ulonglong2*>(&sm[OFF_W3T + k*16]);
            ulonglong2 W0 = wr[0], W1v = wr[1];
            op[0] = fma2(ak, W0.x, op[0]);
            op[1] = fma2(ak, W0.y, op[1]);
            op[2] = fma2(ak, W1v.x, op[2]);
            op[3] = fma2(ak, W1v.y, op[3]);
            ulonglong2 W2v = wr[2], W3v = wr[3];
            op[4] = fma2(ak, W2v.x, op[4]);
            op[5] = fma2(ak, W2v.y, op[5]);
            op[6] = fma2(ak, W3v.x, op[6]);
            op[7] = fma2(ak, W3v.y, op[7]);
            float dz2 = sm[OFF_W3T + k*16 + 0] * (1.0f - __expf(-100.0f * h2k));
            sm[OFF_HB + k*BP + tt] = dz2;
        }
        float o[16];
        #pragma unroll
        for (int i2 = 0; i2 < 8; i2++) {
            float2 v = unpack2(op[i2]);
            o[2*i2+0] = v.x;
            o[2*i2+1] = v.y;
        }
        float sdf = o[0] + sm[OFF_B3 + 0];
        #pragma unroll
        for (int i = 1; i < 16; i++) sm[OFF_F + (i-1)*BP + tt] = o[i] + sm[OFF_B3 + i];
        // Laplace-CDF sigma
        float be  = 0.015f + fabsf(beta[0]);
        float as  = fabsf(sdf);
        float em1 = __expf(-as / be) - 1.0f;
        float sgn = (sdf > 0.0f) ? 1.0f : ((sdf < 0.0f) ? -1.0f : 0.0f);
        float sg  = (0.5f + 0.5f * sgn * em1) / be;
        g_sigma[p] = mask ? sg : 0.0f;
    }
    __syncthreads();

    // ---------- phase 4: L2 bwd GEMM (+ prefetch cw2 stage for phase 5) ----------
    gemm128<64, 2>(sm + OFF_WBIG, sm + OFF_HB, sm + OFF_HA, sm + OFF_B1, tt);
    float4 pcw2[4];
    {
        const float4* cw2v = (const float4*)cw2;
        #pragma unroll
        for (int q = 0; q < 4; q++) pcw2[q] = cw2v[q*256 + tt];
    }
    __syncthreads();

    // ---------- phase 5: store cw2 stage + d_emb (packed) + trilinear bwd ----------
    #pragma unroll
    for (int q = 0; q < 4; q++) {
        int t4 = q*256 + tt;
        int j = t4 >> 4, k4 = t4 & 15;
        float* dst = &sm[OFF_HB + j*65 + 4*k4];
        dst[0] = pcw2[q].x; dst[1] = pcw2[q].y; dst[2] = pcw2[q].z; dst[3] = pcw2[q].w;
    }
    {
        u64 op[8];
        #pragma unroll
        for (int i = 0; i < 8; i++) op[i] = 0ull;
        #pragma unroll 8
        for (int j = 0; j < 64; j++) {
            float d = sm[OFF_HA + j*BP + tt];
            u64 ak = pack2(d, d);
            const ulonglong2* wr = reinterpret_cast<const ulonglong2*>(&sm[OFF_W1 + j*16]);
            ulonglong2 W0 = wr[0], W1v = wr[1];
            op[0] = fma2(ak, W0.x, op[0]);
            op[1] = fma2(ak, W0.y, op[1]);
            op[2] = fma2(ak, W1v.x, op[2]);
            op[3] = fma2(ak, W1v.y, op[3]);
            ulonglong2 W2v = wr[2], W3v = wr[3];
            op[4] = fma2(ak, W2v.x, op[4]);
            op[5] = fma2(ak, W2v.y, op[5]);
            op[6] = fma2(ak, W3v.x, op[6]);
            op[7] = fma2(ak, W3v.y, op[7]);
        }
        float o[16];
        #pragma unroll
        for (int i2 = 0; i2 < 8; i2++) {
            float2 v = unpack2(op[i2]);
            o[2*i2+0] = v.x;
            o[2*i2+1] = v.y;
        }
        // trilinear backward: re-gather corners, dot with o (=d_emb)
        float wx[2] = {1.0f - f[0], f[0]};
        float wy[2] = {1.0f - f[1], f[1]};
        float wz[2] = {1.0f - f[2], f[2]};
        float gx = 0.0f, gy = 0.0f, gz = 0.0f;
        #pragma unroll
        for (int c = 0; c < 8; c++) {
            const int dx = (c >> 2) & 1, dy = (c >> 1) & 1, dz = c & 1;
            const float4* cp = reinterpret_cast<const float4*>(
                grid + (size_t)(base000 + dx*(GS*GS) + dy*GS + dz) * EE);
            float dot = 0.0f;
            #pragma unroll
            for (int q = 0; q < 4; q++) {
                float4 v = cp[q];
                dot = fmaf(o[4*q+0], v.x, dot);
                dot = fmaf(o[4*q+1], v.y, dot);
                dot = fmaf(o[4*q+2], v.z, dot);
                dot = fmaf(o[4*q+3], v.w, dot);
            }
            float sx = dx ? 1.0f : -1.0f;
            float sy = dy ? 1.0f : -1.0f;
            float sz = dz ? 1.0f : -1.0f;
            gx = fmaf(sx * wy[dy] * wz[dz], dot, gx);
            gy = fmaf(wx[dx] * sy * wz[dz], dot, gy);
            gz = fmaf(wx[dx] * wy[dy] * sz, dot, gz);
        }
        const float K = 48.846153846153847f;   // 0.5*(G-1)/BOUND
        float dX = gx * (inb[0] ? K : 0.0f);
        float dY = gy * (inb[1] ? K : 0.0f);
        float dZ = gz * (inb[2] ? K : 0.0f);
        out[RAYS*8 + 3*p + 0] = dX;
        out[RAYS*8 + 3*p + 1] = dY;
        out[RAYS*8 + 3*p + 2] = dZ;
        float nn  = fmaxf(sqrtf(dX*dX + dY*dY + dZ*dZ), 1e-12f);
        float inv = 1.0f / nn;
        sm[OFF_F + 15*BP + tt] = dX * inv;
        sm[OFF_F + 16*BP + tt] = dY * inv;
        sm[OFF_F + 17*BP + tt] = dZ * inv;
    }
    __syncthreads();

    // ---------- phase 6: color L1 GEMM (CW1T dedicated) + CWt2 transpose ----------
    gemm128<18, 1>(sm + OFF_CW1T, sm + OFF_F, sm + OFF_HA, sm + OFF_CB1, tt);
    for (int t = tt; t < 4096; t += NT) { int k = t >> 6, j = t & 63; sm[OFF_WBIG + k*64 + j] = sm[OFF_HB + j*65 + k]; }
    __syncthreads();

    // ---------- phase 8: color L2 GEMM ----------
    gemm128<64, 1>(sm + OFF_WBIG, sm + OFF_HA, sm + OFF_HB, sm + OFF_CB2, tt);
    __syncthreads();

    // ---------- phase 9: color L3 (scalar) ----------
    {
        float a0 = 0.0f, a1 = 0.0f, a2 = 0.0f;
        #pragma unroll 8
        for (int k = 0; k < 64; k++) {
            float hk = sm[OFF_HB + k*BP + tt];
            float4 cw = *(const float4*)&sm[OFF_CW3T + k*4];
            a0 = fmaf(hk, cw.x, a0);
            a1 = fmaf(hk, cw.y, a1);
            a2 = fmaf(hk, cw.z, a2);
        }
        a0 += sm[OFF_CB3 + 0];
        a1 += sm[OFF_CB3 + 1];
        a2 += sm[OFF_CB3 + 2];
        g_rgb[3*p + 0] = 1.0f / (1.0f + __expf(-a0));
        g_rgb[3*p + 1] = 1.0f / (1.0f + __expf(-a1));
        g_rgb[3*p + 2] = 1.0f / (1.0f + __expf(-a2));
    }
}

// ---------------- render: 1 block (64 threads) per ray, shfl scan ----------------
__global__ void __launch_bounds__(64)
render_kernel(const float* __restrict__ rays_d_norm,
              const int* __restrict__ nearp, const int* __restrict__ farp,
              float* __restrict__ out)
{
    __shared__ float red[64*8];
    __shared__ float warp0_total;
    const int r = blockIdx.x;
    const int s = threadIdx.x;
    const int lane = s & 31;
    const int wrp  = s >> 5;
    const int p = r * SAMP + s;

    float nearf = (float)nearp[0];
    float farf  = (float)farp[0];
    float dt    = (farf - nearf) * (1.0f / (float)SAMP);
    const float* grads = out + RAYS*8;

    float dd = g_sigma[p] * dt;

    float cs = dd;
    #pragma unroll
    for (int o = 1; o < 32; o <<= 1) {
        float v = __shfl_up_sync(0xffffffffu, cs, o);
        if (lane >= o) cs += v;
    }
    if (wrp == 0 && lane == 31) warp0_total = cs;
    __syncthreads();
    if (wrp == 1) cs += warp0_total;

    float T = __expf(-(cs - dd));
    float w = (1.0f - __expf(-dd)) * T;

    float rgb0 = g_rgb[3*p + 0], rgb1 = g_rgb[3*p + 1], rgb2 = g_rgb[3*p + 2];
    float gx = grads[3*p + 0], gy = grads[3*p + 1], gz = grads[3*p + 2];
    float nn = fmaxf(sqrtf(gx*gx + gy*gy + gz*gz), 1e-12f);
    float wi = w / nn;
    float tm = nearf + ((float)s + 0.5f) * dt;

    red[s*8 + 0] = w * rgb0;
    red[s*8 + 1] = w * rgb1;
    red[s*8 + 2] = w * rgb2;
    red[s*8 + 3] = w * tm;
    red[s*8 + 4] = wi * gx;
    red[s*8 + 5] = wi * gy;
    red[s*8 + 6] = wi * gz;
    red[s*8 + 7] = w;
    __syncthreads();

    #pragma unroll
    for (int stride = 32; stride >= 1; stride >>= 1) {
        if (s < stride) {
            float4 a0 = *(float4*)&red[s*8];
            float4 a1 = *(float4*)&red[s*8 + 4];
            float4 b0 = *(float4*)&red[(s+stride)*8];
            float4 b1 = *(float4*)&red[(s+stride)*8 + 4];
            a0.x += b0.x; a0.y += b0.y; a0.z += b0.z; a0.w += b0.w;
            a1.x += b1.x; a1.y += b1.y; a1.z += b1.z; a1.w += b1.w;
            *(float4*)&red[s*8] = a0;
            *(float4*)&red[s*8 + 4] = a1;
        }
        __syncthreads();
    }

    if (s == 0) {
        float ir = 1.0f / rays_d_norm[r];
        out[8*r + 0] = red[0];
        out[8*r + 1] = red[1];
        out[8*r + 2] = red[2];
        out[8*r + 3] = red[3] * ir;
        out[8*r + 4] = red[4];
        out[8*r + 5] = red[5];
        out[8*r + 6] = red[6];
        out[8*r + 7] = red[7];
    }
}

extern "C" void kernel_launch(void* const* d_in, const int* in_sizes, int n_in,
                              void* d_out, int out_size)
{
    const float* rays_o      = (const float*)d_in[0];
    const float* rays_d      = (const float*)d_in[1];
    const float* rays_d_norm = (const float*)d_in[2];
    const float* grid        = (const float*)d_in[3];
    const float* sw1 = (const float*)d_in[4];
    const float* sb1 = (const float*)d_in[5];
    const float* sw2 = (const float*)d_in[6];
    const float* sb2 = (const float*)d_in[7];
    const float* sw3 = (const float*)d_in[8];
    const float* sb3 = (const float*)d_in[9];
    const float* cw1 = (const float*)d_in[10];
    const float* cb1 = (const float*)d_in[11];
    const float* cw2 = (const float*)d_in[12];
    const float* cb2 = (const float*)d_in[13];
    const float* cw3 = (const float*)d_in[14];
    const float* cb3 = (const float*)d_in[15];
    const float* beta  = (const float*)d_in[16];
    const int*   nearp = (const int*)d_in[17];
    const int*   farp  = (const int*)d_in[18];
    float* out = (float*)d_out;

    cudaFuncSetAttribute(points_kernel,
                         cudaFuncAttributeMaxDynamicSharedMemorySize, SM_BYTES);

    points_kernel<<<NP/BP, NT, SM_BYTES>>>(rays_o, rays_d, grid,
                                           sw1, sb1, sw2, sb2, sw3, sb3,
                                           cw1, cb1, cw2, cb2, cw3, cb3,
                                           beta, nearp, farp, out);
    render_kernel<<<RAYS, 64>>>(rays_d_norm, nearp, farp, out);
}